// round 7
// baseline (speedup 1.0000x reference)
#include <cuda_runtime.h>
#include <cfloat>

#define NN 100000
#define CC 200
#define EE 400000
#define GG 512
#define HH 4
#define DD 50
#define NC4 (NN * (CC / 4))
#define SCAN_B 1024
#define SCAN_NB ((NN + SCAN_B - 1) / SCAN_B)   // 98

// ---------------- scratch ----------------------------------------------------
__device__ __align__(16) float g_xh[(size_t)NN * CC];
__device__ __align__(16) float g_asrc[NN * HH];
__device__ __align__(16) float g_adst[NN * HH];
__device__ float g_gsum[GG], g_gsq[GG], g_gcnt[GG], g_gmean[GG], g_ginv[GG];
__device__ float g_srel[NN], g_sbase[NN], g_es[NN], g_scale[NN];
__device__ unsigned g_gmu[GG];
__device__ float g_gz[GG];
// CSR
__device__ int g_cnt[NN];
__device__ int g_base[NN];
__device__ int g_cursor[NN];
__device__ int g_csrc[EE];
__device__ int g_bsum[SCAN_NB];
__device__ int g_bsumx[SCAN_NB];

// ---------------- helpers ---------------------------------------------------
__device__ __forceinline__ unsigned fkey(float f) {
    unsigned b = __float_as_uint(f);
    return b ^ ((unsigned)((int)b >> 31) | 0x80000000u);
}
__device__ __forceinline__ float funkey(unsigned u) {
    unsigned b = (u & 0x80000000u) ? (u ^ 0x80000000u) : ~u;
    return __uint_as_float(b);
}
__device__ __forceinline__ float warpSum(float v) {
#pragma unroll
    for (int o = 16; o; o >>= 1) v += __shfl_xor_sync(0xffffffffu, v, o);
    return v;
}
__device__ __forceinline__ float warpMax(float v) {
#pragma unroll
    for (int o = 16; o; o >>= 1) v = fmaxf(v, __shfl_xor_sync(0xffffffffu, v, o));
    return v;
}
__device__ __forceinline__ float lrelu(float a) { return a > 0.f ? a : 0.2f * a; }

__device__ __forceinline__ unsigned long long pack2(float x, float y) {
    unsigned long long r;
    asm("mov.b64 %0, {%1, %2};" : "=l"(r)
        : "r"(__float_as_uint(x)), "r"(__float_as_uint(y)));
    return r;
}
__device__ __forceinline__ void fma2(unsigned long long& d, unsigned long long a,
                                     unsigned long long b) {
    asm("fma.rn.f32x2 %0, %1, %2, %0;" : "+l"(d) : "l"(a), "l"(b));
}
__device__ __forceinline__ float2 unpack2(unsigned long long v) {
    unsigned lo, hi;
    asm("mov.b64 {%0, %1}, %2;" : "=r"(lo), "=r"(hi) : "l"(v));
    return make_float2(__uint_as_float(lo), __uint_as_float(hi));
}
__device__ __forceinline__ void red_add_v4(float* addr, float a, float b, float c, float d) {
    asm volatile("red.global.add.v4.f32 [%0], {%1, %2, %3, %4};"
                 :: "l"(addr), "f"(a), "f"(b), "f"(c), "f"(d) : "memory");
}

// ---------------- kernels ----------------------------------------------------

__global__ void k_init(float* __restrict__ outg) {
    int i = blockIdx.x * blockDim.x + threadIdx.x;
    if (i < NN) g_cnt[i] = 0;
    if (i < GG * (CC / 4))
        *(float4*)&outg[(size_t)i * 4] = make_float4(0.f, 0.f, 0.f, 0.f);
    if (i < GG) {
        g_gsum[i] = 0.f; g_gsq[i] = 0.f; g_gcnt[i] = 0.f;
        g_gmu[i] = 0u; g_gz[i] = 0.f;
    }
}

__global__ void k_ln_stats(const float* __restrict__ x,
                           const int* __restrict__ batch) {
    int gw = (blockIdx.x * blockDim.x + threadIdx.x) >> 5;
    int lane = threadIdx.x & 31;
    if (gw >= NN) return;
    const float* row = &x[(size_t)gw * CC];
    float s = 0.f, s2 = 0.f;
#pragma unroll
    for (int t = 0; t < 2; t++) {
        int c4 = lane + t * 32;
        if (c4 < CC / 4) {
            float4 v = *(const float4*)&row[c4 * 4];
            s += v.x + v.y + v.z + v.w;
            s2 += v.x * v.x + v.y * v.y + v.z * v.z + v.w * v.w;
        }
    }
    s = warpSum(s); s2 = warpSum(s2);
    if (lane == 0) {
        int b = batch[gw];
        atomicAdd(&g_gsum[b], s);
        atomicAdd(&g_gsq[b], s2);
        atomicAdd(&g_gcnt[b], 1.f);
    }
}

__global__ void k_ln_final() {
    int i = blockIdx.x * blockDim.x + threadIdx.x;
    if (i >= GG) return;
    float cnt = g_gcnt[i];
    float mean = 0.f, inv = 0.f;
    if (cnt > 0.f) {
        float denom = cnt * (float)CC;
        mean = g_gsum[i] / denom;
        float var = g_gsq[i] / denom - mean * mean;
        inv = rsqrtf(var + 1e-5f);
    }
    g_gmean[i] = mean;
    g_ginv[i] = inv;
}

// xh = elu(LN(x)) @ W  — LN+ELU fused into A-tile load.
// grid = (4 col-blocks fast, row-blocks slow) for L2 reuse of x.
__global__ void __launch_bounds__(256) k_gemm(const float* __restrict__ x,
                                              const int* __restrict__ batch,
                                              const float* __restrict__ lnw,
                                              const float* __restrict__ lnb,
                                              const float* __restrict__ W) {
    __shared__ __align__(16) float As[8][132];
    __shared__ __align__(16) float Bs[8][64];
    const int bm = blockIdx.y * 128;
    const int bn = blockIdx.x * 64;
    const int tid = threadIdx.x;
    const int tx = tid & 15;
    const int ty = tid >> 4;

    unsigned long long acc[4][4];
#pragma unroll
    for (int i = 0; i < 4; i++)
#pragma unroll
        for (int j = 0; j < 4; j++) acc[i][j] = 0ull;

    const int arow = tid >> 1;
    const int ak0 = (tid & 1) * 4;
    const int bk = tid >> 5;
    const int bc0 = (tid & 31) * 2;

    const int grow = bm + arow;
    float mean = 0.f, inv = 0.f;
    if (grow < NN) {
        int b = batch[grow];
        mean = g_gmean[b];
        inv = g_ginv[b];
    }

    for (int k0 = 0; k0 < CC; k0 += 8) {
        float4 av = make_float4(0.f, 0.f, 0.f, 0.f);
        if (grow < NN) {
            av = *(const float4*)&x[(size_t)grow * CC + k0 + ak0];
            float4 wv = *(const float4*)&lnw[k0 + ak0];
            float4 bv = *(const float4*)&lnb[k0 + ak0];
            av.x = (av.x - mean) * inv * wv.x + bv.x;
            av.y = (av.y - mean) * inv * wv.y + bv.y;
            av.z = (av.z - mean) * inv * wv.z + bv.z;
            av.w = (av.w - mean) * inv * wv.w + bv.w;
            av.x = av.x > 0.f ? av.x : (__expf(av.x) - 1.f);
            av.y = av.y > 0.f ? av.y : (__expf(av.y) - 1.f);
            av.z = av.z > 0.f ? av.z : (__expf(av.z) - 1.f);
            av.w = av.w > 0.f ? av.w : (__expf(av.w) - 1.f);
        }
        As[ak0 + 0][arow] = av.x;
        As[ak0 + 1][arow] = av.y;
        As[ak0 + 2][arow] = av.z;
        As[ak0 + 3][arow] = av.w;

        float2 bv = make_float2(0.f, 0.f);
        int gcol = bn + bc0;
        if (gcol < CC) bv = *(const float2*)&W[(size_t)(k0 + bk) * CC + gcol];
        Bs[bk][bc0] = bv.x;
        Bs[bk][bc0 + 1] = bv.y;
        __syncthreads();

#pragma unroll
        for (int k = 0; k < 8; k++) {
            unsigned long long a2[4];
#pragma unroll
            for (int i = 0; i < 4; i++)
                a2[i] = *(const unsigned long long*)&As[k][ty * 8 + 2 * i];
            float4 b4 = *(const float4*)&Bs[k][tx * 4];
            unsigned long long b2[4];
            b2[0] = pack2(b4.x, b4.x);
            b2[1] = pack2(b4.y, b4.y);
            b2[2] = pack2(b4.z, b4.z);
            b2[3] = pack2(b4.w, b4.w);
#pragma unroll
            for (int i = 0; i < 4; i++)
#pragma unroll
                for (int j = 0; j < 4; j++) fma2(acc[i][j], a2[i], b2[j]);
        }
        __syncthreads();
    }

#pragma unroll
    for (int i = 0; i < 4; i++) {
        int r0 = bm + ty * 8 + 2 * i;
        if (r0 >= NN) break;
        int c = bn + tx * 4;
        if (c >= CC) continue;
        float2 v0 = unpack2(acc[i][0]);
        float2 v1 = unpack2(acc[i][1]);
        float2 v2 = unpack2(acc[i][2]);
        float2 v3 = unpack2(acc[i][3]);
        *(float4*)&g_xh[(size_t)r0 * CC + c] = make_float4(v0.x, v1.x, v2.x, v3.x);
        if (r0 + 1 < NN)
            *(float4*)&g_xh[(size_t)(r0 + 1) * CC + c] = make_float4(v0.y, v1.y, v2.y, v3.y);
    }
}

__global__ void k_att(const float* __restrict__ att_s, const float* __restrict__ att_d) {
    __shared__ float s_as[CC], s_ad[CC];
    for (int i = threadIdx.x; i < CC; i += blockDim.x) {
        s_as[i] = att_s[i];
        s_ad[i] = att_d[i];
    }
    __syncthreads();
    int gw = (blockIdx.x * blockDim.x + threadIdx.x) >> 5;
    int lane = threadIdx.x & 31;
    if (gw >= NN) return;
    const float* row = &g_xh[(size_t)gw * CC];
#pragma unroll
    for (int hh = 0; hh < HH; hh++) {
        float ss = 0.f, sd = 0.f;
#pragma unroll
        for (int t = 0; t < 2; t++) {
            int d = lane + t * 32;
            if (d < DD) {
                float v = row[hh * DD + d];
                ss += v * s_as[hh * DD + d];
                sd += v * s_ad[hh * DD + d];
            }
        }
        ss = warpSum(ss); sd = warpSum(sd);
        if (lane == 0) {
            g_asrc[gw * HH + hh] = ss;
            g_adst[gw * HH + hh] = sd;
        }
    }
}

// ---- CSR build ----
__global__ void k_count(const int* __restrict__ ei) {
    int i = blockIdx.x * blockDim.x + threadIdx.x;
    if (i >= EE) return;
    atomicAdd(&g_cnt[ei[EE + i]], 1);
}

__global__ void k_scan_block() {
    __shared__ int sm[SCAN_B];
    int i = blockIdx.x * SCAN_B + threadIdx.x;
    int v = (i < NN) ? g_cnt[i] : 0;
    sm[threadIdx.x] = v;
    __syncthreads();
    for (int o = 1; o < SCAN_B; o <<= 1) {
        int t = (threadIdx.x >= o) ? sm[threadIdx.x - o] : 0;
        __syncthreads();
        sm[threadIdx.x] += t;
        __syncthreads();
    }
    if (i < NN) g_base[i] = sm[threadIdx.x] - v;
    if (threadIdx.x == SCAN_B - 1) g_bsum[blockIdx.x] = sm[threadIdx.x];
}

__global__ void k_scan_top() {
    if (threadIdx.x == 0) {
        int run = 0;
        for (int b = 0; b < SCAN_NB; b++) {
            g_bsumx[b] = run;
            run += g_bsum[b];
        }
    }
}

__global__ void k_scan_add() {
    int i = blockIdx.x * blockDim.x + threadIdx.x;
    if (i >= NN) return;
    int v = g_base[i] + g_bsumx[i / SCAN_B];
    g_base[i] = v;
    g_cursor[i] = v;
}

__global__ void k_fill(const int* __restrict__ ei) {
    int i = blockIdx.x * blockDim.x + threadIdx.x;
    if (i >= EE) return;
    int dst = ei[EE + i];
    int pos = atomicAdd(&g_cursor[dst], 1);
    g_csrc[pos] = ei[i];
}

// ---- GAT softmax + aggregation + SAG score projections, one warp per node ----
__global__ void __launch_bounds__(256) k_gat(float* __restrict__ out,
                                             const float* __restrict__ bias,
                                             const float* __restrict__ w_rel,
                                             const float* __restrict__ w_root,
                                             const float* __restrict__ b_rel) {
    __shared__ float s_e[8][32][4];
    __shared__ int s_src[8][32];
    int w = threadIdx.x >> 5;
    int lane = threadIdx.x & 31;
    int n = blockIdx.x * 8 + w;
    if (n >= NN) return;
    int base = g_base[n];
    int deg = g_cnt[n];

    float4 ad = *(const float4*)&g_adst[n * 4];
    float4 asn = *(const float4*)&g_asrc[n * 4];
    float sf0 = lrelu(asn.x + ad.x), sf1 = lrelu(asn.y + ad.y);
    float sf2 = lrelu(asn.z + ad.z), sf3 = lrelu(asn.w + ad.w);

    float m0 = sf0, m1 = sf1, m2 = sf2, m3 = sf3;
    for (int j = lane; j < deg; j += 32) {
        int src = g_csrc[base + j];
        float4 as = *(const float4*)&g_asrc[src * 4];
        m0 = fmaxf(m0, lrelu(as.x + ad.x));
        m1 = fmaxf(m1, lrelu(as.y + ad.y));
        m2 = fmaxf(m2, lrelu(as.z + ad.z));
        m3 = fmaxf(m3, lrelu(as.w + ad.w));
    }
    m0 = warpMax(m0); m1 = warpMax(m1); m2 = warpMax(m2); m3 = warpMax(m3);

    float acc[7];
#pragma unroll
    for (int t = 0; t < 7; t++) acc[t] = 0.f;
    float z0 = 0.f, z1 = 0.f, z2 = 0.f, z3 = 0.f;

    for (int c0 = 0; c0 < deg; c0 += 32) {
        int j = c0 + lane;
        int cn = min(32, deg - c0);
        if (j < deg) {
            int src = g_csrc[base + j];
            s_src[w][lane] = src;
            float4 as = *(const float4*)&g_asrc[src * 4];
            float e0 = __expf(lrelu(as.x + ad.x) - m0);
            float e1 = __expf(lrelu(as.y + ad.y) - m1);
            float e2 = __expf(lrelu(as.z + ad.z) - m2);
            float e3 = __expf(lrelu(as.w + ad.w) - m3);
            s_e[w][lane][0] = e0; s_e[w][lane][1] = e1;
            s_e[w][lane][2] = e2; s_e[w][lane][3] = e3;
            z0 += e0; z1 += e1; z2 += e2; z3 += e3;
        }
        __syncwarp();
        for (int jj = 0; jj < cn; jj++) {
            int src = s_src[w][jj];
            float e0 = s_e[w][jj][0], e1 = s_e[w][jj][1];
            float e2 = s_e[w][jj][2], e3 = s_e[w][jj][3];
            const float* xr = &g_xh[(size_t)src * CC];
#pragma unroll
            for (int t = 0; t < 7; t++) {
                int c = lane + t * 32;
                if (c < CC) {
                    int hh = c / DD;
                    float e = hh == 0 ? e0 : hh == 1 ? e1 : hh == 2 ? e2 : e3;
                    acc[t] += xr[c] * e;
                }
            }
        }
        __syncwarp();
    }
    z0 = warpSum(z0); z1 = warpSum(z1); z2 = warpSum(z2); z3 = warpSum(z3);

    float es0 = __expf(sf0 - m0), es1 = __expf(sf1 - m1);
    float es2 = __expf(sf2 - m2), es3 = __expf(sf3 - m3);
    z0 += es0 + 1e-16f; z1 += es1 + 1e-16f;
    z2 += es2 + 1e-16f; z3 += es3 + 1e-16f;
    const float* xn = &g_xh[(size_t)n * CC];
    float* orow = &out[(size_t)n * CC];
    float sr = 0.f, sb = 0.f;
#pragma unroll
    for (int t = 0; t < 7; t++) {
        int c = lane + t * 32;
        if (c < CC) {
            int hh = c / DD;
            float es = hh == 0 ? es0 : hh == 1 ? es1 : hh == 2 ? es2 : es3;
            float z = hh == 0 ? z0 : hh == 1 ? z1 : hh == 2 ? z2 : z3;
            float v = (acc[t] + xn[c] * es) / z + __ldg(&bias[c]);
            orow[c] = v;
            sr += v * __ldg(&w_rel[c]);
            sb += v * __ldg(&w_root[c]);
        }
    }
    sr = warpSum(sr); sb = warpSum(sb);
    if (lane == 0) {
        g_srel[n] = sr;
        g_sbase[n] = sb + __ldg(&b_rel[0]);
    }
}

// agg via CSR + per-graph max
__global__ void k_score_agg(const int* __restrict__ batch) {
    int i = blockIdx.x * blockDim.x + threadIdx.x;
    if (i >= NN) return;
    int base = g_base[i], deg = g_cnt[i];
    float s = 0.f;
    for (int j = 0; j < deg; j++) s += g_srel[g_csrc[base + j]];
    s += g_sbase[i];
    g_sbase[i] = s;
    atomicMax(&g_gmu[batch[i]], fkey(s));
}

__global__ void k_score_exp(const int* __restrict__ batch) {
    int i = blockIdx.x * blockDim.x + threadIdx.x;
    if (i >= NN) return;
    int b = batch[i];
    float es = expf(g_sbase[i] - funkey(g_gmu[b]));
    g_es[i] = es;
    atomicAdd(&g_gz[b], es);
}

__global__ void k_scale(const int* __restrict__ batch) {
    int i = blockIdx.x * blockDim.x + threadIdx.x;
    if (i >= NN) return;
    g_scale[i] = g_es[i] / g_gz[batch[i]];
}

__global__ void k_finalize(float* __restrict__ out, float* __restrict__ outg,
                           const int* __restrict__ batch) {
    int i = blockIdx.x * blockDim.x + threadIdx.x;
    if (i >= NC4) return;
    int n = i / (CC / 4);
    int c = (i - n * (CC / 4)) * 4;
    float sc = g_scale[n];
    float4 v = *(const float4*)&out[(size_t)n * CC + c];
    v.x *= sc; v.y *= sc; v.z *= sc; v.w *= sc;
    *(float4*)&out[(size_t)n * CC + c] = v;
    red_add_v4(&outg[(size_t)batch[n] * CC + c], v.x, v.y, v.z, v.w);
}

// ---------------- launch ----------------------------------------------------
extern "C" void kernel_launch(void* const* d_in, const int* in_sizes, int n_in,
                              void* d_out, int out_size) {
    const float* x = (const float*)d_in[0];
    const int* ei = (const int*)d_in[1];
    const int* batch = (const int*)d_in[2];
    const float* ln_w = (const float*)d_in[3];
    const float* ln_b = (const float*)d_in[4];
    const float* W_gat = (const float*)d_in[5];
    const float* att_s = (const float*)d_in[6];
    const float* att_d = (const float*)d_in[7];
    const float* bias = (const float*)d_in[8];
    const float* w_rel = (const float*)d_in[9];
    const float* b_rel = (const float*)d_in[10];
    const float* w_root = (const float*)d_in[11];

    float* out = (float*)d_out;
    float* outg = out + (size_t)NN * CC;

    const int T = 256;
    const int blocksV4 = (NC4 + T - 1) / T;
    const int warpNodeBlocks = (NN + 7) / 8;
    const int nodeBlocks = (NN + T - 1) / T;
    const int edgeBlocks = (EE + T - 1) / T;
    (void)in_sizes; (void)n_in; (void)out_size;

    k_init<<<nodeBlocks, T>>>(outg);
    k_ln_stats<<<warpNodeBlocks, T>>>(x, batch);
    k_ln_final<<<(GG + T - 1) / T, T>>>();

    dim3 gemmGrid(4, (NN + 127) / 128);
    k_gemm<<<gemmGrid, 256>>>(x, batch, ln_w, ln_b, W_gat);

    k_att<<<warpNodeBlocks, T>>>(att_s, att_d);

    k_count<<<edgeBlocks, T>>>(ei);
    k_scan_block<<<SCAN_NB, SCAN_B>>>();
    k_scan_top<<<1, 32>>>();
    k_scan_add<<<(NN + SCAN_B - 1) / SCAN_B, SCAN_B>>>();
    k_fill<<<edgeBlocks, T>>>(ei);

    k_gat<<<warpNodeBlocks, T>>>(out, bias, w_rel, w_root, b_rel);

    k_score_agg<<<nodeBlocks, T>>>(batch);
    k_score_exp<<<nodeBlocks, T>>>(batch);
    k_scale<<<nodeBlocks, T>>>(batch);
    k_finalize<<<blocksV4, T>>>(out, outg, batch);
}

// round 9
// speedup vs baseline: 1.1580x; 1.1580x over previous
#include <cuda_runtime.h>
#include <cuda_bf16.h>
#include <cfloat>
#include <cstdint>

#define NN 100000
#define CC 200
#define EE 400000
#define GG 512
#define HH 4
#define DD 50
#define NC4 (NN * (CC / 4))
#define SCAN_B 1024
#define SCAN_NB ((NN + SCAN_B - 1) / SCAN_B)
#define KP 104                 // padded K in u32 units (208 bf16)
#define NTILES 26              // 8-col n-tiles (200 -> 25 real + 1 zero)
#define KTILES 13              // 16-row k-tiles (200 -> 208)

// ---------------- scratch ----------------------------------------------------
__device__ __align__(16) float g_xh[(size_t)NN * CC];
__device__ __align__(16) float g_asrc[NN * HH];
__device__ __align__(16) float g_adst[NN * HH];
__device__ float g_gsum[GG], g_gsq[GG], g_gcnt[GG], g_gmean[GG], g_ginv[GG];
__device__ float g_srel[NN], g_sbase[NN], g_es[NN], g_scale[NN];
__device__ unsigned g_gmu[GG];
__device__ float g_gz[GG];
// packed bf16 A images (fragment-friendly row-major, K padded to 208)
__device__ __align__(16) uint32_t g_Ahi[(size_t)NN * KP];
__device__ __align__(16) uint32_t g_Alo[(size_t)NN * KP];
// fragment-packed B images: [ntile][ktile][lane] -> u64 (b0 | b1<<32)
__device__ __align__(16) unsigned long long g_Bphi[NTILES * KTILES * 32];
__device__ __align__(16) unsigned long long g_Bplo[NTILES * KTILES * 32];
// CSR
__device__ int g_cnt[NN];
__device__ int g_base[NN];
__device__ int g_cursor[NN];
__device__ int g_csrc[EE];
__device__ int g_bsum[SCAN_NB];
__device__ int g_bsumx[SCAN_NB];

// ---------------- helpers ----------------------------------------------------
__device__ __forceinline__ unsigned fkey(float f) {
    unsigned b = __float_as_uint(f);
    return b ^ ((unsigned)((int)b >> 31) | 0x80000000u);
}
__device__ __forceinline__ float funkey(unsigned u) {
    unsigned b = (u & 0x80000000u) ? (u ^ 0x80000000u) : ~u;
    return __uint_as_float(b);
}
__device__ __forceinline__ float warpSum(float v) {
#pragma unroll
    for (int o = 16; o; o >>= 1) v += __shfl_xor_sync(0xffffffffu, v, o);
    return v;
}
__device__ __forceinline__ float warpMax(float v) {
#pragma unroll
    for (int o = 16; o; o >>= 1) v = fmaxf(v, __shfl_xor_sync(0xffffffffu, v, o));
    return v;
}
__device__ __forceinline__ float lrelu(float a) { return a > 0.f ? a : 0.2f * a; }
__device__ __forceinline__ void red_add_v4(float* addr, float a, float b, float c, float d) {
    asm volatile("red.global.add.v4.f32 [%0], {%1, %2, %3, %4};"
                 :: "l"(addr), "f"(a), "f"(b), "f"(c), "f"(d) : "memory");
}
__device__ __forceinline__ unsigned short f2bf(float v) {
    __nv_bfloat16 b = __float2bfloat16(v);
    return *reinterpret_cast<unsigned short*>(&b);
}
__device__ __forceinline__ float bf2f(unsigned short u) {
    __nv_bfloat16 b;
    *reinterpret_cast<unsigned short*>(&b) = u;
    return __bfloat162float(b);
}
// bf16 HMMA: D(16x8,f32) += A(16x16,bf16) * B(16x8,bf16)
__device__ __forceinline__ void mma16816(float* c, const uint32_t* a,
                                         uint32_t b0, uint32_t b1) {
    asm volatile(
        "mma.sync.aligned.m16n8k16.row.col.f32.bf16.bf16.f32 "
        "{%0,%1,%2,%3}, {%4,%5,%6,%7}, {%8,%9}, {%0,%1,%2,%3};"
        : "+f"(c[0]), "+f"(c[1]), "+f"(c[2]), "+f"(c[3])
        : "r"(a[0]), "r"(a[1]), "r"(a[2]), "r"(a[3]), "r"(b0), "r"(b1));
}

// ---------------- kernels ----------------------------------------------------

__global__ void k_init(float* __restrict__ outg) {
    int i = blockIdx.x * blockDim.x + threadIdx.x;
    if (i < NN) g_cnt[i] = 0;
    if (i < GG * (CC / 4))
        *(float4*)&outg[(size_t)i * 4] = make_float4(0.f, 0.f, 0.f, 0.f);
    if (i < GG) {
        g_gsum[i] = 0.f; g_gsq[i] = 0.f; g_gcnt[i] = 0.f;
        g_gmu[i] = 0u; g_gz[i] = 0.f;
    }
}

// pack W into per-lane mma B fragments (hi/lo bf16 split)
__global__ void k_bprep(const float* __restrict__ W) {
    int i = blockIdx.x * blockDim.x + threadIdx.x;
    if (i >= NTILES * KTILES * 32) return;
    int lane = i & 31;
    int kt = (i >> 5) % KTILES;
    int nt = (i >> 5) / KTILES;
    int n = nt * 8 + (lane >> 2);
    int k0 = kt * 16 + (lane & 3) * 2;
    float w00 = 0.f, w01 = 0.f, w10 = 0.f, w11 = 0.f;
    if (n < CC) {
        if (k0 < CC) w00 = W[k0 * CC + n];
        if (k0 + 1 < CC) w01 = W[(k0 + 1) * CC + n];
        if (k0 + 8 < CC) w10 = W[(k0 + 8) * CC + n];
        if (k0 + 9 < CC) w11 = W[(k0 + 9) * CC + n];
    }
    unsigned short h00 = f2bf(w00), h01 = f2bf(w01), h10 = f2bf(w10), h11 = f2bf(w11);
    unsigned short l00 = f2bf(w00 - bf2f(h00)), l01 = f2bf(w01 - bf2f(h01));
    unsigned short l10 = f2bf(w10 - bf2f(h10)), l11 = f2bf(w11 - bf2f(h11));
    uint32_t bh0 = (uint32_t)h00 | ((uint32_t)h01 << 16);
    uint32_t bh1 = (uint32_t)h10 | ((uint32_t)h11 << 16);
    uint32_t bl0 = (uint32_t)l00 | ((uint32_t)l01 << 16);
    uint32_t bl1 = (uint32_t)l10 | ((uint32_t)l11 << 16);
    g_Bphi[i] = (unsigned long long)bh0 | ((unsigned long long)bh1 << 32);
    g_Bplo[i] = (unsigned long long)bl0 | ((unsigned long long)bl1 << 32);
}

__global__ void k_ln_stats(const float* __restrict__ x,
                           const int* __restrict__ batch) {
    int gw = (blockIdx.x * blockDim.x + threadIdx.x) >> 5;
    int lane = threadIdx.x & 31;
    if (gw >= NN) return;
    const float* row = &x[(size_t)gw * CC];
    float s = 0.f, s2 = 0.f;
#pragma unroll
    for (int t = 0; t < 2; t++) {
        int c4 = lane + t * 32;
        if (c4 < CC / 4) {
            float4 v = *(const float4*)&row[c4 * 4];
            s += v.x + v.y + v.z + v.w;
            s2 += v.x * v.x + v.y * v.y + v.z * v.z + v.w * v.w;
        }
    }
    s = warpSum(s); s2 = warpSum(s2);
    if (lane == 0) {
        int b = batch[gw];
        atomicAdd(&g_gsum[b], s);
        atomicAdd(&g_gsq[b], s2);
        atomicAdd(&g_gcnt[b], 1.f);
    }
}

__global__ void k_ln_final() {
    int i = blockIdx.x * blockDim.x + threadIdx.x;
    if (i >= GG) return;
    float cnt = g_gcnt[i];
    float mean = 0.f, inv = 0.f;
    if (cnt > 0.f) {
        float denom = cnt * (float)CC;
        mean = g_gsum[i] / denom;
        float var = g_gsq[i] / denom - mean * mean;
        inv = rsqrtf(var + 1e-5f);
    }
    g_gmean[i] = mean;
    g_ginv[i] = inv;
}

// A prep: h = elu(LN(x)) -> packed bf16 hi/lo rows (K padded 200->208)
__global__ void k_aprep(const float* __restrict__ x, const int* __restrict__ batch,
                        const float* __restrict__ lnw, const float* __restrict__ lnb) {
    int i = blockIdx.x * blockDim.x + threadIdx.x;
    if (i >= NN * KP) return;
    int row = i / KP, cp = i - row * KP;
    int k = cp * 2;
    float v0 = 0.f, v1 = 0.f;
    if (k < CC) {
        int b = batch[row];
        float mean = g_gmean[b], inv = g_ginv[b];
        float2 xv = *(const float2*)&x[(size_t)row * CC + k];
        v0 = (xv.x - mean) * inv * __ldg(&lnw[k]) + __ldg(&lnb[k]);
        v1 = (xv.y - mean) * inv * __ldg(&lnw[k + 1]) + __ldg(&lnb[k + 1]);
        v0 = v0 > 0.f ? v0 : (__expf(v0) - 1.f);
        v1 = v1 > 0.f ? v1 : (__expf(v1) - 1.f);
    }
    unsigned short h0 = f2bf(v0), h1 = f2bf(v1);
    unsigned short l0 = f2bf(v0 - bf2f(h0)), l1 = f2bf(v1 - bf2f(h1));
    g_Ahi[i] = (uint32_t)h0 | ((uint32_t)h1 << 16);
    g_Alo[i] = (uint32_t)l0 | ((uint32_t)l1 << 16);
}

// ---- HMMA GEMM: xh = h @ W via split-bf16 (3 mmas), warp = 16 rows x 13 ntiles
__global__ void __launch_bounds__(256) k_gemm_mma() {
    int w = blockIdx.x * 8 + (threadIdx.x >> 5);
    int lane = threadIdx.x & 31;
    int tile = w >> 1, half = w & 1;
    if (tile >= NN / 16) return;
    int m0 = tile * 16;
    int r = m0 + (lane >> 2);

    float acc[13][4];
#pragma unroll
    for (int nt = 0; nt < 13; nt++)
#pragma unroll
        for (int q = 0; q < 4; q++) acc[nt][q] = 0.f;

    const int aoff = lane & 3;
    for (int kt = 0; kt < KTILES; kt++) {
        uint32_t ahi[4], alo[4];
        size_t i0 = (size_t)r * KP + kt * 8 + aoff;
        size_t i1 = (size_t)(r + 8) * KP + kt * 8 + aoff;
        ahi[0] = g_Ahi[i0]; ahi[1] = g_Ahi[i1];
        ahi[2] = g_Ahi[i0 + 4]; ahi[3] = g_Ahi[i1 + 4];
        alo[0] = g_Alo[i0]; alo[1] = g_Alo[i1];
        alo[2] = g_Alo[i0 + 4]; alo[3] = g_Alo[i1 + 4];
#pragma unroll
        for (int nt = 0; nt < 13; nt++) {
            int ng = half * 13 + nt;
            unsigned long long bh = g_Bphi[(ng * KTILES + kt) * 32 + lane];
            unsigned long long bl = g_Bplo[(ng * KTILES + kt) * 32 + lane];
            uint32_t bh0 = (uint32_t)bh, bh1 = (uint32_t)(bh >> 32);
            uint32_t bl0 = (uint32_t)bl, bl1 = (uint32_t)(bl >> 32);
            mma16816(acc[nt], ahi, bh0, bh1);
            mma16816(acc[nt], ahi, bl0, bl1);
            mma16816(acc[nt], alo, bh0, bh1);
        }
    }

#pragma unroll
    for (int nt = 0; nt < 13; nt++) {
        int n0 = (half * 13 + nt) * 8;
        if (n0 >= CC) break;
        int col = n0 + (lane & 3) * 2;
        *(float2*)&g_xh[(size_t)r * CC + col] = make_float2(acc[nt][0], acc[nt][1]);
        *(float2*)&g_xh[(size_t)(r + 8) * CC + col] = make_float2(acc[nt][2], acc[nt][3]);
    }
}

__global__ void k_att(const float* __restrict__ att_s, const float* __restrict__ att_d) {
    __shared__ float s_as[CC], s_ad[CC];
    for (int i = threadIdx.x; i < CC; i += blockDim.x) {
        s_as[i] = att_s[i];
        s_ad[i] = att_d[i];
    }
    __syncthreads();
    int gw = (blockIdx.x * blockDim.x + threadIdx.x) >> 5;
    int lane = threadIdx.x & 31;
    if (gw >= NN) return;
    const float* row = &g_xh[(size_t)gw * CC];
#pragma unroll
    for (int hh = 0; hh < HH; hh++) {
        float ss = 0.f, sd = 0.f;
#pragma unroll
        for (int t = 0; t < 2; t++) {
            int d = lane + t * 32;
            if (d < DD) {
                float v = row[hh * DD + d];
                ss += v * s_as[hh * DD + d];
                sd += v * s_ad[hh * DD + d];
            }
        }
        ss = warpSum(ss); sd = warpSum(sd);
        if (lane == 0) {
            g_asrc[gw * HH + hh] = ss;
            g_adst[gw * HH + hh] = sd;
        }
    }
}

// ---- CSR build ----
__global__ void k_count(const int* __restrict__ ei) {
    int i = blockIdx.x * blockDim.x + threadIdx.x;
    if (i >= EE) return;
    atomicAdd(&g_cnt[ei[EE + i]], 1);
}

__global__ void k_scan_block() {
    __shared__ int sm[SCAN_B];
    int i = blockIdx.x * SCAN_B + threadIdx.x;
    int v = (i < NN) ? g_cnt[i] : 0;
    sm[threadIdx.x] = v;
    __syncthreads();
    for (int o = 1; o < SCAN_B; o <<= 1) {
        int t = (threadIdx.x >= o) ? sm[threadIdx.x - o] : 0;
        __syncthreads();
        sm[threadIdx.x] += t;
        __syncthreads();
    }
    if (i < NN) g_base[i] = sm[threadIdx.x] - v;
    if (threadIdx.x == SCAN_B - 1) g_bsum[blockIdx.x] = sm[threadIdx.x];
}

__global__ void k_scan_top() {
    if (threadIdx.x == 0) {
        int run = 0;
        for (int b = 0; b < SCAN_NB; b++) {
            g_bsumx[b] = run;
            run += g_bsum[b];
        }
    }
}

__global__ void k_scan_add() {
    int i = blockIdx.x * blockDim.x + threadIdx.x;
    if (i >= NN) return;
    int v = g_base[i] + g_bsumx[i / SCAN_B];
    g_base[i] = v;
    g_cursor[i] = v;
}

__global__ void k_fill(const int* __restrict__ ei) {
    int i = blockIdx.x * blockDim.x + threadIdx.x;
    if (i >= EE) return;
    int dst = ei[EE + i];
    int pos = atomicAdd(&g_cursor[dst], 1);
    g_csrc[pos] = ei[i];
}

// ---- GAT softmax + aggregation + SAG score projections ----
__global__ void __launch_bounds__(256) k_gat(float* __restrict__ out,
                                             const float* __restrict__ bias,
                                             const float* __restrict__ w_rel,
                                             const float* __restrict__ w_root,
                                             const float* __restrict__ b_rel) {
    __shared__ float s_e[8][32][4];
    __shared__ int s_src[8][32];
    int w = threadIdx.x >> 5;
    int lane = threadIdx.x & 31;
    int n = blockIdx.x * 8 + w;
    if (n >= NN) return;
    int base = g_base[n];
    int deg = g_cnt[n];

    float4 ad = *(const float4*)&g_adst[n * 4];
    float4 asn = *(const float4*)&g_asrc[n * 4];
    float sf0 = lrelu(asn.x + ad.x), sf1 = lrelu(asn.y + ad.y);
    float sf2 = lrelu(asn.z + ad.z), sf3 = lrelu(asn.w + ad.w);

    float m0 = sf0, m1 = sf1, m2 = sf2, m3 = sf3;
    for (int j = lane; j < deg; j += 32) {
        int src = g_csrc[base + j];
        float4 as = *(const float4*)&g_asrc[src * 4];
        m0 = fmaxf(m0, lrelu(as.x + ad.x));
        m1 = fmaxf(m1, lrelu(as.y + ad.y));
        m2 = fmaxf(m2, lrelu(as.z + ad.z));
        m3 = fmaxf(m3, lrelu(as.w + ad.w));
    }
    m0 = warpMax(m0); m1 = warpMax(m1); m2 = warpMax(m2); m3 = warpMax(m3);

    float acc[7];
#pragma unroll
    for (int t = 0; t < 7; t++) acc[t] = 0.f;
    float z0 = 0.f, z1 = 0.f, z2 = 0.f, z3 = 0.f;

    for (int c0 = 0; c0 < deg; c0 += 32) {
        int j = c0 + lane;
        int cn = min(32, deg - c0);
        if (j < deg) {
            int src = g_csrc[base + j];
            s_src[w][lane] = src;
            float4 as = *(const float4*)&g_asrc[src * 4];
            float e0 = __expf(lrelu(as.x + ad.x) - m0);
            float e1 = __expf(lrelu(as.y + ad.y) - m1);
            float e2 = __expf(lrelu(as.z + ad.z) - m2);
            float e3 = __expf(lrelu(as.w + ad.w) - m3);
            s_e[w][lane][0] = e0; s_e[w][lane][1] = e1;
            s_e[w][lane][2] = e2; s_e[w][lane][3] = e3;
            z0 += e0; z1 += e1; z2 += e2; z3 += e3;
        }
        __syncwarp();
        for (int jj = 0; jj < cn; jj++) {
            int src = s_src[w][jj];
            float e0 = s_e[w][jj][0], e1 = s_e[w][jj][1];
            float e2 = s_e[w][jj][2], e3 = s_e[w][jj][3];
            const float* xr = &g_xh[(size_t)src * CC];
#pragma unroll
            for (int t = 0; t < 7; t++) {
                int c = lane + t * 32;
                if (c < CC) {
                    int hh = c / DD;
                    float e = hh == 0 ? e0 : hh == 1 ? e1 : hh == 2 ? e2 : e3;
                    acc[t] += xr[c] * e;
                }
            }
        }
        __syncwarp();
    }
    z0 = warpSum(z0); z1 = warpSum(z1); z2 = warpSum(z2); z3 = warpSum(z3);

    float es0 = __expf(sf0 - m0), es1 = __expf(sf1 - m1);
    float es2 = __expf(sf2 - m2), es3 = __expf(sf3 - m3);
    z0 += es0 + 1e-16f; z1 += es1 + 1e-16f;
    z2 += es2 + 1e-16f; z3 += es3 + 1e-16f;
    const float* xn = &g_xh[(size_t)n * CC];
    float* orow = &out[(size_t)n * CC];
    float sr = 0.f, sb = 0.f;
#pragma unroll
    for (int t = 0; t < 7; t++) {
        int c = lane + t * 32;
        if (c < CC) {
            int hh = c / DD;
            float es = hh == 0 ? es0 : hh == 1 ? es1 : hh == 2 ? es2 : es3;
            float z = hh == 0 ? z0 : hh == 1 ? z1 : hh == 2 ? z2 : z3;
            float v = (acc[t] + xn[c] * es) / z + __ldg(&bias[c]);
            orow[c] = v;
            sr += v * __ldg(&w_rel[c]);
            sb += v * __ldg(&w_root[c]);
        }
    }
    sr = warpSum(sr); sb = warpSum(sb);
    if (lane == 0) {
        g_srel[n] = sr;
        g_sbase[n] = sb + __ldg(&b_rel[0]);
    }
}

__global__ void k_score_agg(const int* __restrict__ batch) {
    int i = blockIdx.x * blockDim.x + threadIdx.x;
    if (i >= NN) return;
    int base = g_base[i], deg = g_cnt[i];
    float s = 0.f;
    for (int j = 0; j < deg; j++) s += g_srel[g_csrc[base + j]];
    s += g_sbase[i];
    g_sbase[i] = s;
    atomicMax(&g_gmu[batch[i]], fkey(s));
}

__global__ void k_score_exp(const int* __restrict__ batch) {
    int i = blockIdx.x * blockDim.x + threadIdx.x;
    if (i >= NN) return;
    int b = batch[i];
    float es = expf(g_sbase[i] - funkey(g_gmu[b]));
    g_es[i] = es;
    atomicAdd(&g_gz[b], es);
}

__global__ void k_scale(const int* __restrict__ batch) {
    int i = blockIdx.x * blockDim.x + threadIdx.x;
    if (i >= NN) return;
    g_scale[i] = g_es[i] / g_gz[batch[i]];
}

__global__ void k_finalize(float* __restrict__ out, float* __restrict__ outg,
                           const int* __restrict__ batch) {
    int i = blockIdx.x * blockDim.x + threadIdx.x;
    if (i >= NC4) return;
    int n = i / (CC / 4);
    int c = (i - n * (CC / 4)) * 4;
    float sc = g_scale[n];
    float4 v = *(const float4*)&out[(size_t)n * CC + c];
    v.x *= sc; v.y *= sc; v.z *= sc; v.w *= sc;
    *(float4*)&out[(size_t)n * CC + c] = v;
    red_add_v4(&outg[(size_t)batch[n] * CC + c], v.x, v.y, v.z, v.w);
}

// ---------------- launch ----------------------------------------------------
extern "C" void kernel_launch(void* const* d_in, const int* in_sizes, int n_in,
                              void* d_out, int out_size) {
    const float* x = (const float*)d_in[0];
    const int* ei = (const int*)d_in[1];
    const int* batch = (const int*)d_in[2];
    const float* ln_w = (const float*)d_in[3];
    const float* ln_b = (const float*)d_in[4];
    const float* W_gat = (const float*)d_in[5];
    const float* att_s = (const float*)d_in[6];
    const float* att_d = (const float*)d_in[7];
    const float* bias = (const float*)d_in[8];
    const float* w_rel = (const float*)d_in[9];
    const float* b_rel = (const float*)d_in[10];
    const float* w_root = (const float*)d_in[11];

    float* out = (float*)d_out;
    float* outg = out + (size_t)NN * CC;

    const int T = 256;
    const int blocksV4 = (NC4 + T - 1) / T;
    const int warpNodeBlocks = (NN + 7) / 8;
    const int nodeBlocks = (NN + T - 1) / T;
    const int edgeBlocks = (EE + T - 1) / T;
    (void)in_sizes; (void)n_in; (void)out_size;

    k_init<<<nodeBlocks, T>>>(outg);
    k_bprep<<<(NTILES * KTILES * 32 + T - 1) / T, T>>>(W_gat);
    k_ln_stats<<<warpNodeBlocks, T>>>(x, batch);
    k_ln_final<<<(GG + T - 1) / T, T>>>();
    k_aprep<<<(NN * KP + T - 1) / T, T>>>(x, batch, ln_w, ln_b);

    // 6250 row-tiles x 2 halves = 12500 warps; 8 warps/CTA
    k_gemm_mma<<<(12500 + 7) / 8, 256>>>();

    k_att<<<warpNodeBlocks, T>>>(att_s, att_d);

    k_count<<<edgeBlocks, T>>>(ei);
    k_scan_block<<<SCAN_NB, SCAN_B>>>();
    k_scan_top<<<1, 32>>>();
    k_scan_add<<<(NN + SCAN_B - 1) / SCAN_B, SCAN_B>>>();
    k_fill<<<edgeBlocks, T>>>(ei);

    k_gat<<<warpNodeBlocks, T>>>(out, bias, w_rel, w_root, b_rel);

    k_score_agg<<<nodeBlocks, T>>>(batch);
    k_score_exp<<<nodeBlocks, T>>>(batch);
    k_scale<<<nodeBlocks, T>>>(batch);
    k_finalize<<<blocksV4, T>>>(out, outg, batch);
}